// round 1
// baseline (speedup 1.0000x reference)
#include <cuda_runtime.h>
#include <stdint.h>

// KVCache concat + truncate:
//   B=4, H=32, L=4096, D=128, S=1, context_length=4096.
//   k_new[b,h,l] = k_cache[b,h,l+1]  (l in [0,4095))
//   k_new[b,h,4095] = k[b,h,0]
//   same for v. Output = [k_new | v_new] in d_out.
//
// Implementation: the shifted copy is globally contiguous EXCEPT that at each
// (b,h) boundary the last row (l=4095) bleeds into the next bh's row 0. So:
//   1) one big D2D memcpyAsync per tensor, shifted by D elements
//   2) tiny fixup kernel overwriting every (b,h)'s last row with the new token

static constexpr long long Bsz = 4;
static constexpr long long Hh  = 32;
static constexpr long long Ll  = 4096;
static constexpr long long Dd  = 128;
static constexpr long long PER = Bsz * Hh * Ll * Dd;   // 67,108,864 elements
static constexpr long long ROWS = Bsz * Hh;            // 128 (b,h) rows
static constexpr long long FIX_ELEMS = ROWS * Dd;      // 16,384 elements per tensor

__global__ void kv_fixup_kernel(const float* __restrict__ knew,
                                const float* __restrict__ vnew,
                                float* __restrict__ out)
{
    // One thread per float4 of the seam rows: ROWS * D / 4 = 4096 threads
    int idx = blockIdx.x * blockDim.x + threadIdx.x;
    const int total = (int)(FIX_ELEMS / 4);
    if (idx >= total) return;

    int bh = idx / (int)(Dd / 4);         // which (b,h)
    int d4 = idx % (int)(Dd / 4);         // which float4 within the row

    const float4* k4 = reinterpret_cast<const float4*>(knew);
    const float4* v4 = reinterpret_cast<const float4*>(vnew);
    float4* o4 = reinterpret_cast<float4*>(out);

    // Destination: out[bh*(L*D) + (L-1)*D + d] for k, + PER for v
    long long row_base4 = ((long long)bh * (Ll * Dd) + (Ll - 1) * Dd) / 4;
    long long src4 = (long long)bh * (Dd / 4) + d4;

    o4[row_base4 + d4]             = k4[src4];
    o4[PER / 4 + row_base4 + d4]   = v4[src4];
}

extern "C" void kernel_launch(void* const* d_in, const int* in_sizes, int n_in,
                              void* d_out, int out_size)
{
    const float* k_cache = (const float*)d_in[0];
    const float* v_cache = (const float*)d_in[1];
    const float* k_new   = (const float*)d_in[2];
    const float* v_new   = (const float*)d_in[3];
    // d_in[4] = context_length (unused; shapes are fixed for this bench)

    float* out = (float*)d_out;

    // Bulk shifted copies (graph-capturable async D2D). Each copies
    // (PER - D) floats: out[0 .. PER-D) = cache[D .. PER).
    const size_t bytes = (size_t)(PER - Dd) * sizeof(float);
    cudaMemcpyAsync(out,        k_cache + Dd, bytes, cudaMemcpyDeviceToDevice);
    cudaMemcpyAsync(out + PER,  v_cache + Dd, bytes, cudaMemcpyDeviceToDevice);

    // Patch the 128 seam rows (per tensor) with the new tokens.
    const int total = (int)(FIX_ELEMS / 4);    // 4096 float4 stores
    const int threads = 256;
    const int blocks = (total + threads - 1) / threads;
    kv_fixup_kernel<<<blocks, threads>>>(k_new, v_new, out);
}

// round 2
// speedup vs baseline: 2.0653x; 2.0653x over previous
#include <cuda_runtime.h>
#include <stdint.h>

// KVCache concat + truncate, single fused streaming-copy kernel.
//   B=4, H=32, L=4096, D=128, S=1, context_length=4096.
//   out[t][b,h,l]   = cache[t][b,h,l+1]   for l < L-1
//   out[t][b,h,L-1] = new [t][b,h,0]
//   t=0 -> k, t=1 -> v; out = [k_new | v_new].
//
// One grid-stride float4 kernel covers the whole 1.07 GB of traffic,
// including the 128 seam rows per tensor (predicated source select).

static constexpr int  Dd   = 128;
static constexpr int  Ll   = 4096;
static constexpr long long PER = 4LL * 32 * 4096 * 128;  // 67,108,864 floats per tensor

static constexpr int PER4  = (int)(PER / 4);     // 16,777,216 float4 per tensor
static constexpr int LD4   = (Ll * Dd) / 4;      // 131,072 float4 per (b,h)
static constexpr int SEAM4 = LD4 - Dd / 4;       // 131,040: start of seam row (float4 units)
static constexpr int D4    = Dd / 4;             // 32

__global__ void __launch_bounds__(256)
kv_shift_kernel(const float4* __restrict__ k_cache,
                const float4* __restrict__ v_cache,
                const float4* __restrict__ k_new,
                const float4* __restrict__ v_new,
                float4* __restrict__ out)
{
    const int stride = gridDim.x * blockDim.x;
    const int total4 = 2 * PER4;                 // both tensors

    for (int i = blockIdx.x * blockDim.x + threadIdx.x; i < total4; i += stride) {
        int t      = (i >= PER4);                // 0 = k, 1 = v
        int within = i - t * PER4;               // float4 index inside tensor
        int bh     = within / LD4;               // which (b,h)
        int pos    = within - bh * LD4;          // float4 index within (b,h)

        const float4* cache = t ? v_cache : k_cache;
        const float4* fresh = t ? v_new   : k_new;

        float4 val;
        if (pos >= SEAM4) {
            // seam: last row of this (b,h) comes from the new token
            val = fresh[bh * D4 + (pos - SEAM4)];
        } else {
            // shifted copy: out[within] = cache[within + D/4]
            val = cache[within + D4];
        }
        out[i] = val;
    }
}

extern "C" void kernel_launch(void* const* d_in, const int* in_sizes, int n_in,
                              void* d_out, int out_size)
{
    const float4* k_cache = (const float4*)d_in[0];
    const float4* v_cache = (const float4*)d_in[1];
    const float4* k_new   = (const float4*)d_in[2];
    const float4* v_new   = (const float4*)d_in[3];
    // d_in[4] = context_length (constant 4096 for this bench)

    float4* out = (float4*)d_out;

    // 1184 blocks = 148 SMs * 8 blocks; grid-stride covers 33.5M float4s.
    kv_shift_kernel<<<1184, 256>>>(k_cache, v_cache, k_new, v_new, out);
}